// round 12
// baseline (speedup 1.0000x reference)
#include <cuda_runtime.h>
#include <cuda_fp16.h>
#include <math.h>
#include <stdint.h>

// ===========================================================================
// out[M,N] = x[M,K] @ (w * nm_mask(w))[N,K]^T + bias[N]
// M=16384, N=2048, K=2048 fp32.
// fp16 mma.sync (fp32 accum), rel_err ~2.9e-4.
// Persistent GEMM: 148 CTAs x 512 thr (16 warps 4x4, warp tile 32x32).
// A loaded as fp32 from input (LDG->cvt->STS, no x-prep kernel).
// B from small W-prep kernel via cp.async. 3-slot smem ring, 1 bar/iter.
// ===========================================================================

__device__ __half g_wh[2048 * 2048];

#define MDIM 16384
#define NDIM 2048
#define KDIM 2048
#define NTILES ((MDIM / 128) * (NDIM / 128))   // 2048
#define GRID_P 148

// ---------------- helpers ---------------------------------------------------
__device__ __forceinline__ uint32_t smem_u32(const void* p) {
    uint32_t a;
    asm("{ .reg .u64 t; cvta.to.shared.u64 t, %1; cvt.u32.u64 %0, t; }"
        : "=r"(a) : "l"(p));
    return a;
}
__device__ __forceinline__ void cp16(uint32_t sm, const void* g) {
    asm volatile("cp.async.cg.shared.global [%0], [%1], 16;" :: "r"(sm), "l"(g));
}
#define CP_COMMIT() asm volatile("cp.async.commit_group;" ::: "memory")
#define CP_WAIT1()  asm volatile("cp.async.wait_group 1;"  ::: "memory")

__device__ __forceinline__ void ldm4(uint32_t r[4], uint32_t addr) {
    asm volatile("ldmatrix.sync.aligned.m8n8.x4.shared.b16 {%0,%1,%2,%3}, [%4];"
                 : "=r"(r[0]), "=r"(r[1]), "=r"(r[2]), "=r"(r[3]) : "r"(addr));
}
__device__ __forceinline__ void mma16816(float c[4], const uint32_t a[4],
                                         const uint32_t b0, const uint32_t b1) {
    asm volatile(
        "mma.sync.aligned.m16n8k16.row.col.f32.f16.f16.f32 "
        "{%0,%1,%2,%3}, {%4,%5,%6,%7}, {%8,%9}, {%0,%1,%2,%3};"
        : "+f"(c[0]), "+f"(c[1]), "+f"(c[2]), "+f"(c[3])
        : "r"(a[0]), "r"(a[1]), "r"(a[2]), "r"(a[3]), "r"(b0), "r"(b1));
}
__device__ __forceinline__ uint32_t f2h2(float a, float b) {
    __half2 h = __float22half2_rn(make_float2(a, b));
    return *reinterpret_cast<uint32_t*>(&h);
}

// ---------------- config ----------------------------------------------------
#define NTH 512
#define NSLOT 3
#define STG_A 0              // 16 KB (128 rows x 128 B fp16)
#define STG_B 16384          // 16 KB
#define SLOT_SZ 32768
#define SMEM_TOTAL (NSLOT * SLOT_SZ)   // 96 KB

// ===========================================================================
// W prep: 2:4 mask (stable-argsort semantics) + fp16 convert
// ===========================================================================
__device__ __forceinline__ uint2 mask_quad_to_h4(float4 v) {
    float vals[4] = {v.x, v.y, v.z, v.w};
    float a[4] = {fabsf(v.x), fabsf(v.y), fabsf(v.z), fabsf(v.w)};
    int z1 = 0;
    #pragma unroll
    for (int i = 1; i < 4; i++) if (a[i] < a[z1]) z1 = i;
    a[z1] = INFINITY;
    int z2 = 0;
    #pragma unroll
    for (int i = 1; i < 4; i++) if (a[i] < a[z2]) z2 = i;
    vals[z1] = 0.0f;
    vals[z2] = 0.0f;
    uint2 o;
    o.x = f2h2(vals[0], vals[1]);
    o.y = f2h2(vals[2], vals[3]);
    return o;
}

__global__ void prep_w_kernel(const float* __restrict__ w, int n_units) {
    int u = blockIdx.x * blockDim.x + threadIdx.x;
    if (u >= n_units) return;
    const float4* wq = reinterpret_cast<const float4*>(w);
    float4 v0 = wq[u * 2 + 0];
    float4 v1 = wq[u * 2 + 1];
    uint2 a = mask_quad_to_h4(v0);
    uint2 b = mask_quad_to_h4(v1);
    reinterpret_cast<uint4*>(g_wh)[u] = make_uint4(a.x, a.y, b.x, b.y);
}

// ===========================================================================
// Persistent GEMM
// ===========================================================================
// B loader (fp16 cp.async): 1024 16B cells, 2 per thread
__device__ __forceinline__ void load_B(uint32_t sb, int slot, int bn, int k0,
                                       int tid) {
    const uint32_t st = sb + slot * SLOT_SZ + STG_B;
    #pragma unroll
    for (int u = 0; u < 2; u++) {
        int cell = tid + u * NTH;
        int row = cell >> 3, c = cell & 7;
        uint32_t so = (uint32_t)(row << 7) + ((c ^ (row & 7)) << 4);
        cp16(st + so, g_wh + (size_t)(bn * 128 + row) * KDIM + k0 + c * 8);
    }
}
// A: LDG fp32 (16 floats into regs)
__device__ __forceinline__ void ldg_A(float4 r[4], const float* __restrict__ x,
                                      int bm, int k0, int tid) {
    #pragma unroll
    for (int u = 0; u < 2; u++) {
        int cell = tid + u * NTH;
        int row = cell >> 3, c = cell & 7;
        const float4* src = reinterpret_cast<const float4*>(
            x + (size_t)(bm * 128 + row) * KDIM + k0 + c * 8);
        r[2 * u + 0] = src[0];
        r[2 * u + 1] = src[1];
    }
}
// A: cvt + STS
__device__ __forceinline__ void sts_A(char* smem, int slot, const float4 r[4],
                                      int tid) {
    #pragma unroll
    for (int u = 0; u < 2; u++) {
        int cell = tid + u * NTH;
        int row = cell >> 3, c = cell & 7;
        uint32_t so = (uint32_t)(row << 7) + ((c ^ (row & 7)) << 4);
        const float4& p = r[2 * u + 0];
        const float4& q = r[2 * u + 1];
        *reinterpret_cast<uint4*>(smem + slot * SLOT_SZ + STG_A + so) =
            make_uint4(f2h2(p.x, p.y), f2h2(p.z, p.w),
                       f2h2(q.x, q.y), f2h2(q.z, q.w));
    }
}

__global__ __launch_bounds__(NTH, 1)
void gemm_persist_kernel(const float* __restrict__ x,
                         const float* __restrict__ bias,
                         float* __restrict__ C) {
    extern __shared__ char smem[];
    const uint32_t sb = smem_u32(smem);
    const int tid = threadIdx.x;
    const int wid = tid >> 5;
    const int lid = tid & 31;
    const int bid = blockIdx.x;

    const int wm = wid >> 2;          // 0..3 -> 32-row A band
    const int wn = wid & 3;           // 0..3 -> 32-row B band

    const int a_r  = lid & 15;
    const int a_ch = lid >> 4;
    const int b_r  = (lid & 7) + ((lid >> 4) << 3);
    const int b_ch = (lid >> 3) & 1;

    // linear chunk index l: tile = bid + (l>>5)*GRID_P, k-chunk = l&31
    const int ntile_cta = (NTILES - 1 - bid) / GRID_P + 1;
    const int lmax = ntile_cta * 32;

    float acc[2][4][4];
    #pragma unroll
    for (int i = 0; i < 2; i++)
        #pragma unroll
        for (int j = 0; j < 4; j++)
            #pragma unroll
            for (int r = 0; r < 4; r++)
                acc[i][j][r] = 0.0f;

    // prologue: chunks 0 and 1 (both in tile0)
    int t0 = bid;
    int bn0 = t0 & 15, bm0 = t0 >> 4;
    load_B(sb, 0, bn0, 0, tid);  CP_COMMIT();
    load_B(sb, 1, bn0, 64, tid); CP_COMMIT();
    {
        float4 r0[4], r1[4];
        ldg_A(r0, x, bm0, 0, tid);
        ldg_A(r1, x, bm0, 64, tid);
        sts_A(smem, 0, r0, tid);
        sts_A(smem, 1, r1, tid);
    }

    float4 rp[4];
    for (int l = 0; l < lmax; l++) {
        const int i = l & 31;
        const int t = bid + (l >> 5) * GRID_P;
        const int bn = t & 15, bm = t >> 4;
        const int slot = l % NSLOT;
        const int slot2 = (l + 2) % NSLOT;

        CP_WAIT1();
        __syncthreads();

        // prefetch chunk l+2 (may belong to next tile)
        const bool pf = (l + 2 < lmax);
        if (pf) {
            const int lp = l + 2;
            const int tp = bid + (lp >> 5) * GRID_P;
            const int bnp = tp & 15, bmp = tp >> 4;
            const int k0p = (lp & 31) * 64;
            load_B(sb, slot2, bnp, k0p, tid);
            ldg_A(rp, x, bmp, k0p, tid);
        }
        CP_COMMIT();

        // MMA on slot
        const uint32_t A = sb + slot * SLOT_SZ + STG_A;
        const uint32_t B = sb + slot * SLOT_SZ + STG_B;
        #pragma unroll
        for (int kk = 0; kk < 4; kk++) {
            uint32_t af[2][4], bf[4][2];
            #pragma unroll
            for (int mt = 0; mt < 2; mt++) {
                int row = wm * 32 + mt * 16 + a_r;
                int c = (kk << 1) + a_ch;
                ldm4(af[mt], A + (row << 7) + ((c ^ (row & 7)) << 4));
            }
            #pragma unroll
            for (int bt = 0; bt < 2; bt++) {
                int row = wn * 32 + bt * 16 + b_r;
                int c = (kk << 1) + b_ch;
                uint32_t rb[4];
                ldm4(rb, B + (row << 7) + ((c ^ (row & 7)) << 4));
                bf[2 * bt + 0][0] = rb[0]; bf[2 * bt + 0][1] = rb[1];
                bf[2 * bt + 1][0] = rb[2]; bf[2 * bt + 1][1] = rb[3];
            }
            #pragma unroll
            for (int mt = 0; mt < 2; mt++)
                #pragma unroll
                for (int nt = 0; nt < 4; nt++)
                    mma16816(acc[mt][nt], af[mt], bf[nt][0], bf[nt][1]);
        }

        // store prefetched A into freed slot (safe: slot2 freed by barrier above)
        if (pf) sts_A(smem, slot2, rp, tid);

        // tile finished -> direct-STG epilogue (no smem, no barrier)
        if (i == 31) {
            #pragma unroll
            for (int nt = 0; nt < 4; nt++) {
                int col = bn * 128 + wn * 32 + nt * 8 + ((lid & 3) << 1);
                float2 bv = *reinterpret_cast<const float2*>(bias + col);
                #pragma unroll
                for (int mt = 0; mt < 2; mt++) {
                    int row = bm * 128 + wm * 32 + mt * 16 + (lid >> 2);
                    *reinterpret_cast<float2*>(C + (size_t)row * NDIM + col) =
                        make_float2(acc[mt][nt][0] + bv.x, acc[mt][nt][1] + bv.y);
                    *reinterpret_cast<float2*>(C + (size_t)(row + 8) * NDIM + col) =
                        make_float2(acc[mt][nt][2] + bv.x, acc[mt][nt][3] + bv.y);
                }
            }
            #pragma unroll
            for (int mt = 0; mt < 2; mt++)
                #pragma unroll
                for (int nt = 0; nt < 4; nt++)
                    #pragma unroll
                    for (int r = 0; r < 4; r++)
                        acc[mt][nt][r] = 0.0f;
        }
    }
}

// ===========================================================================
// Launch
// ===========================================================================
extern "C" void kernel_launch(void* const* d_in, const int* in_sizes, int n_in,
                              void* d_out, int out_size) {
    const float* x    = (const float*)d_in[0];  // [M,K]
    const float* w    = (const float*)d_in[1];  // [N,K]
    const float* bias = (const float*)d_in[2];  // [N]
    float* out = (float*)d_out;                 // [M,N]

    const int n_wu = NDIM * KDIM / 8;
    prep_w_kernel<<<(n_wu + 255) / 256, 256>>>(w, n_wu);

    cudaFuncSetAttribute(gemm_persist_kernel,
                         cudaFuncAttributeMaxDynamicSharedMemorySize, SMEM_TOTAL);
    gemm_persist_kernel<<<GRID_P, NTH, SMEM_TOTAL>>>(x, bias, out);
}

// round 13
// speedup vs baseline: 1.3142x; 1.3142x over previous
#include <cuda_runtime.h>
#include <cuda_fp16.h>
#include <math.h>
#include <stdint.h>

// ===========================================================================
// out[M,N] = x[M,K] @ (w * nm_mask(w))[N,K]^T + bias[N]
// M=16384, N=2048, K=2048 fp32.
// fp16 mma.sync (fp32 accum), rel_err ~2.9e-4.
// Fused producer/consumer: blocks [0,128) convert w(mask)+x to fp16 in
// k-chunk order, setting done[kc] flags; blocks [128, 128+2048) run the
// R8-proven GEMM (CTA 128x128, 256 thr, 8 warps 2x4, 3-stage cp.async,
// 2 CTAs/SM), gating each chunk's loads on the flags.
// ===========================================================================

__device__ __half g_xh[16384 * 2048];
__device__ __half g_wh[2048 * 2048];
__device__ int    g_done[32];

#define MDIM 16384
#define NDIM 2048
#define KDIM 2048
#define NPREP 128
#define NTILES 2048          // (16384/128)*(2048/128)

// ---------------- helpers ---------------------------------------------------
__device__ __forceinline__ uint32_t smem_u32(const void* p) {
    uint32_t a;
    asm("{ .reg .u64 t; cvta.to.shared.u64 t, %1; cvt.u32.u64 %0, t; }"
        : "=r"(a) : "l"(p));
    return a;
}
__device__ __forceinline__ void cp16(uint32_t sm, const void* g) {
    asm volatile("cp.async.cg.shared.global [%0], [%1], 16;" :: "r"(sm), "l"(g));
}
#define CP_COMMIT() asm volatile("cp.async.commit_group;" ::: "memory")
#define CP_WAIT1()  asm volatile("cp.async.wait_group 1;"  ::: "memory")
#define CP_WAIT0()  asm volatile("cp.async.wait_group 0;"  ::: "memory")

__device__ __forceinline__ void ldm4(uint32_t r[4], uint32_t addr) {
    asm volatile("ldmatrix.sync.aligned.m8n8.x4.shared.b16 {%0,%1,%2,%3}, [%4];"
                 : "=r"(r[0]), "=r"(r[1]), "=r"(r[2]), "=r"(r[3]) : "r"(addr));
}
__device__ __forceinline__ void mma16816(float c[4], const uint32_t a[4],
                                         const uint32_t b0, const uint32_t b1) {
    asm volatile(
        "mma.sync.aligned.m16n8k16.row.col.f32.f16.f16.f32 "
        "{%0,%1,%2,%3}, {%4,%5,%6,%7}, {%8,%9}, {%0,%1,%2,%3};"
        : "+f"(c[0]), "+f"(c[1]), "+f"(c[2]), "+f"(c[3])
        : "r"(a[0]), "r"(a[1]), "r"(a[2]), "r"(a[3]), "r"(b0), "r"(b1));
}
__device__ __forceinline__ uint32_t f2h2(float a, float b) {
    __half2 h = __float22half2_rn(make_float2(a, b));
    return *reinterpret_cast<uint32_t*>(&h);
}

// ---------------- GEMM config ----------------------------------------------
#define BM 128
#define BN 128
#define BKE 64
#define NTH 256
#define NSTAGE 3
#define STG_A 0
#define STG_B 16384
#define STAGE_SZ 32768
#define SMEM_TOTAL (NSTAGE * STAGE_SZ)   // 96 KB

// ===========================================================================
// Flag reset (graph-replay safe)
// ===========================================================================
__global__ void zero_flags_kernel() {
    if (threadIdx.x < 32) g_done[threadIdx.x] = 0;
}

// ===========================================================================
// Producer: mask+convert, k-chunk-major.  Unit u: 8 floats of one row's
// 64-col slice. u<16384*8 -> x rows; else -> w rows (masked).
// ===========================================================================
__device__ __forceinline__ uint2 mask_quad_to_h4(float4 v) {
    float vals[4] = {v.x, v.y, v.z, v.w};
    float a[4] = {fabsf(v.x), fabsf(v.y), fabsf(v.z), fabsf(v.w)};
    int z1 = 0;
    #pragma unroll
    for (int i = 1; i < 4; i++) if (a[i] < a[z1]) z1 = i;
    a[z1] = INFINITY;
    int z2 = 0;
    #pragma unroll
    for (int i = 1; i < 4; i++) if (a[i] < a[z2]) z2 = i;
    vals[z1] = 0.0f;
    vals[z2] = 0.0f;
    uint2 o;
    o.x = f2h2(vals[0], vals[1]);
    o.y = f2h2(vals[2], vals[3]);
    return o;
}

__device__ void producer_body(const float* __restrict__ x,
                              const float* __restrict__ w,
                              int cta, int tid) {
    const int NU = (MDIM + NDIM) * 8;            // 147456 units per kc
    for (int kc = 0; kc < 32; kc++) {
        const int k0 = kc * 64;
        for (int u = cta * NTH + tid; u < NU; u += NPREP * NTH) {
            const int c8 = u & 7;
            const int r = u >> 3;
            if (r < MDIM) {
                const float4* src = reinterpret_cast<const float4*>(
                    x + (size_t)r * KDIM + k0 + c8 * 8);
                float4 v0 = src[0], v1 = src[1];
                *reinterpret_cast<uint4*>(g_xh + (size_t)r * KDIM + k0 + c8 * 8) =
                    make_uint4(f2h2(v0.x, v0.y), f2h2(v0.z, v0.w),
                               f2h2(v1.x, v1.y), f2h2(v1.z, v1.w));
            } else {
                const int rw = r - MDIM;
                const float4* src = reinterpret_cast<const float4*>(
                    w + (size_t)rw * KDIM + k0 + c8 * 8);
                uint2 a = mask_quad_to_h4(src[0]);
                uint2 b = mask_quad_to_h4(src[1]);
                *reinterpret_cast<uint4*>(g_wh + (size_t)rw * KDIM + k0 + c8 * 8) =
                    make_uint4(a.x, a.y, b.x, b.y);
            }
        }
        __syncthreads();
        __threadfence();
        if (tid == 0) atomicAdd(&g_done[kc], 1);
    }
}

// ===========================================================================
// Consumer GEMM pieces (R8-proven)
// ===========================================================================
__device__ __forceinline__ void wait_chunk(int kc, int tid) {
    if (tid == 0) {
        while (((volatile int*)g_done)[kc] < NPREP) {}
    }
    __syncthreads();
}

__device__ __forceinline__ void load_stage(uint32_t sb, int slot, int chunk,
                                           int bm, int bn, int tid) {
    const int k0 = chunk * BKE;
    const uint32_t st = sb + slot * STAGE_SZ;
    #pragma unroll
    for (int t = tid; t < 1024; t += NTH) {       // A: 128 rows x 8 cells
        int row = t >> 3, c = t & 7;
        uint32_t so = (uint32_t)(row << 7) + ((c ^ (row & 7)) << 4);
        cp16(st + STG_A + so, g_xh + (size_t)(bm * BM + row) * KDIM + k0 + c * 8);
    }
    #pragma unroll
    for (int t = tid; t < 1024; t += NTH) {       // B
        int row = t >> 3, c = t & 7;
        uint32_t so = (uint32_t)(row << 7) + ((c ^ (row & 7)) << 4);
        cp16(st + STG_B + so, g_wh + (size_t)(bn * BN + row) * KDIM + k0 + c * 8);
    }
}

__global__ __launch_bounds__(NTH, 2)
void fused_kernel(const float* __restrict__ x,
                  const float* __restrict__ w,
                  const float* __restrict__ bias,
                  float* __restrict__ C) {
    extern __shared__ char smem[];
    const int tid = threadIdx.x;

    if (blockIdx.x < NPREP) {
        producer_body(x, w, blockIdx.x, tid);
        return;
    }

    const uint32_t sb = smem_u32(smem);
    const int wid = tid >> 5;
    const int lid = tid & 31;
    const int t = blockIdx.x - NPREP;
    const int bn = t & 15;
    const int bm = t >> 4;

    const int wm = wid >> 2;
    const int wn = wid & 3;

    const int a_r  = lid & 15;
    const int a_ch = lid >> 4;
    const int b_r  = (lid & 7) + ((lid >> 4) << 3);
    const int b_ch = (lid >> 3) & 1;

    float acc[4][4][4];
    #pragma unroll
    for (int i = 0; i < 4; i++)
        #pragma unroll
        for (int j = 0; j < 4; j++)
            #pragma unroll
            for (int r = 0; r < 4; r++)
                acc[i][j][r] = 0.0f;

    const int NIT = KDIM / BKE;       // 32
    wait_chunk(0, tid);
    load_stage(sb, 0, 0, bm, bn, tid); CP_COMMIT();
    wait_chunk(1, tid);
    load_stage(sb, 1, 1, bm, bn, tid); CP_COMMIT();

    int s = 0, sl = 2;
    for (int i = 0; i < NIT; i++) {
        CP_WAIT1();
        __syncthreads();
        if (i + 2 < NIT) {
            wait_chunk(i + 2, tid);
            load_stage(sb, sl, i + 2, bm, bn, tid);
        }
        CP_COMMIT();

        const uint32_t A = sb + s * STAGE_SZ + STG_A;
        const uint32_t B = sb + s * STAGE_SZ + STG_B;
        #pragma unroll
        for (int kk = 0; kk < 4; kk++) {
            uint32_t af[4][4], bf[4][2];
            #pragma unroll
            for (int mt = 0; mt < 4; mt++) {
                int row = wm * 64 + mt * 16 + a_r;
                int c = (kk << 1) + a_ch;
                ldm4(af[mt], A + (row << 7) + ((c ^ (row & 7)) << 4));
            }
            #pragma unroll
            for (int bt = 0; bt < 2; bt++) {
                int row = wn * 32 + bt * 16 + b_r;
                int c = (kk << 1) + b_ch;
                uint32_t rb[4];
                ldm4(rb, B + (row << 7) + ((c ^ (row & 7)) << 4));
                bf[2 * bt + 0][0] = rb[0]; bf[2 * bt + 0][1] = rb[1];
                bf[2 * bt + 1][0] = rb[2]; bf[2 * bt + 1][1] = rb[3];
            }
            #pragma unroll
            for (int mt = 0; mt < 4; mt++)
                #pragma unroll
                for (int nt = 0; nt < 4; nt++)
                    mma16816(acc[mt][nt], af[mt], bf[nt][0], bf[nt][1]);
        }
        s  = (s  == NSTAGE - 1) ? 0 : s + 1;
        sl = (sl == NSTAGE - 1) ? 0 : sl + 1;
    }

    // ---------------- epilogue ----------------------------------------------
    CP_WAIT0();
    __syncthreads();
    float* stg = reinterpret_cast<float*>(smem);   // [128][132]
    #pragma unroll
    for (int mt = 0; mt < 4; mt++)
        #pragma unroll
        for (int nt = 0; nt < 4; nt++) {
            int r0 = wm * 64 + mt * 16 + (lid >> 2);
            int col = wn * 32 + nt * 8 + ((lid & 3) << 1);
            *reinterpret_cast<float2*>(&stg[r0 * 132 + col]) =
                make_float2(acc[mt][nt][0], acc[mt][nt][1]);
            *reinterpret_cast<float2*>(&stg[(r0 + 8) * 132 + col]) =
                make_float2(acc[mt][nt][2], acc[mt][nt][3]);
        }
    __syncthreads();
    {
        int c4 = (tid & 31) << 2;
        int r0 = (tid >> 5) << 4;
        float4 b4 = *reinterpret_cast<const float4*>(bias + bn * BN + c4);
        #pragma unroll
        for (int rr = 0; rr < 16; rr++) {
            int row = r0 + rr;
            float4 v = *reinterpret_cast<float4*>(&stg[row * 132 + c4]);
            v.x += b4.x; v.y += b4.y; v.z += b4.z; v.w += b4.w;
            *reinterpret_cast<float4*>(
                C + (size_t)(bm * BM + row) * NDIM + bn * BN + c4) = v;
        }
    }
}

// ===========================================================================
// Launch
// ===========================================================================
extern "C" void kernel_launch(void* const* d_in, const int* in_sizes, int n_in,
                              void* d_out, int out_size) {
    const float* x    = (const float*)d_in[0];  // [M,K]
    const float* w    = (const float*)d_in[1];  // [N,K]
    const float* bias = (const float*)d_in[2];  // [N]
    float* out = (float*)d_out;                 // [M,N]

    zero_flags_kernel<<<1, 32>>>();

    cudaFuncSetAttribute(fused_kernel,
                         cudaFuncAttributeMaxDynamicSharedMemorySize, SMEM_TOTAL);
    fused_kernel<<<NPREP + NTILES, NTH, SMEM_TOTAL>>>(x, w, bias, out);
}

// round 14
// speedup vs baseline: 1.4415x; 1.0969x over previous
#include <cuda_runtime.h>
#include <cuda_fp16.h>
#include <math.h>
#include <stdint.h>

// ===========================================================================
// out[M,N] = x[M,K] @ (w * nm_mask(w))[N,K]^T + bias[N]
// M=16384, N=2048, K=2048 fp32.
// fp16 mma.sync (fp32 accum), rel_err ~2.9e-4.
// Fused coarse producer/consumer: blocks [0,128) convert w (masked) then
// x row-blocks in order, flagging completion; blocks [128,128+2048) wait
// ONCE for (w, x-block bm), then run the R8-proven GEMM
// (CTA 128x128, 256 thr, 8 warps 2x4, 3-stage cp.async, 2 CTAs/SM).
// ===========================================================================

__device__ __half g_xh[16384 * 2048];
__device__ __half g_wh[2048 * 2048];
__device__ int    g_done_w;
__device__ int    g_done_x[128];

#define MDIM 16384
#define NDIM 2048
#define KDIM 2048
#define NPREP 128
#define NTILES 2048          // (16384/128)*(2048/128)

// ---------------- helpers ---------------------------------------------------
__device__ __forceinline__ uint32_t smem_u32(const void* p) {
    uint32_t a;
    asm("{ .reg .u64 t; cvta.to.shared.u64 t, %1; cvt.u32.u64 %0, t; }"
        : "=r"(a) : "l"(p));
    return a;
}
__device__ __forceinline__ void cp16(uint32_t sm, const void* g) {
    asm volatile("cp.async.cg.shared.global [%0], [%1], 16;" :: "r"(sm), "l"(g));
}
#define CP_COMMIT() asm volatile("cp.async.commit_group;" ::: "memory")
#define CP_WAIT1()  asm volatile("cp.async.wait_group 1;"  ::: "memory")
#define CP_WAIT0()  asm volatile("cp.async.wait_group 0;"  ::: "memory")

__device__ __forceinline__ void ldm4(uint32_t r[4], uint32_t addr) {
    asm volatile("ldmatrix.sync.aligned.m8n8.x4.shared.b16 {%0,%1,%2,%3}, [%4];"
                 : "=r"(r[0]), "=r"(r[1]), "=r"(r[2]), "=r"(r[3]) : "r"(addr));
}
__device__ __forceinline__ void mma16816(float c[4], const uint32_t a[4],
                                         const uint32_t b0, const uint32_t b1) {
    asm volatile(
        "mma.sync.aligned.m16n8k16.row.col.f32.f16.f16.f32 "
        "{%0,%1,%2,%3}, {%4,%5,%6,%7}, {%8,%9}, {%0,%1,%2,%3};"
        : "+f"(c[0]), "+f"(c[1]), "+f"(c[2]), "+f"(c[3])
        : "r"(a[0]), "r"(a[1]), "r"(a[2]), "r"(a[3]), "r"(b0), "r"(b1));
}
__device__ __forceinline__ uint32_t f2h2(float a, float b) {
    __half2 h = __float22half2_rn(make_float2(a, b));
    return *reinterpret_cast<uint32_t*>(&h);
}

// ---------------- GEMM config ----------------------------------------------
#define BM 128
#define BN 128
#define BKE 64
#define NTH 256
#define NSTAGE 3
#define STG_A 0
#define STG_B 16384
#define STAGE_SZ 32768
#define SMEM_TOTAL (NSTAGE * STAGE_SZ)   // 96 KB

// ===========================================================================
// Flag reset (graph-replay safe)
// ===========================================================================
__global__ void zero_flags_kernel() {
    if (threadIdx.x == 0) g_done_w = 0;
    if (threadIdx.x < 128) g_done_x[threadIdx.x] = 0;
}

// ===========================================================================
// Producer helpers
// ===========================================================================
__device__ __forceinline__ uint2 mask_quad_to_h4(float4 v) {
    float vals[4] = {v.x, v.y, v.z, v.w};
    float a[4] = {fabsf(v.x), fabsf(v.y), fabsf(v.z), fabsf(v.w)};
    int z1 = 0;
    #pragma unroll
    for (int i = 1; i < 4; i++) if (a[i] < a[z1]) z1 = i;
    a[z1] = INFINITY;
    int z2 = 0;
    #pragma unroll
    for (int i = 1; i < 4; i++) if (a[i] < a[z2]) z2 = i;
    vals[z1] = 0.0f;
    vals[z2] = 0.0f;
    uint2 o;
    o.x = f2h2(vals[0], vals[1]);
    o.y = f2h2(vals[2], vals[3]);
    return o;
}

__device__ void producer_body(const float* __restrict__ x,
                              const float* __restrict__ w,
                              int cta, int tid) {
    const int gt = cta * NTH + tid;              // 0..32767
    const int NTHREADS = NPREP * NTH;            // 32768

    // ---- phase 0: w (masked), 2048*2048 floats = 524288 units of 8 --------
    for (int u = gt; u < NDIM * KDIM / 8; u += NTHREADS) {
        const float4* src = reinterpret_cast<const float4*>(w) + u * 2;
        uint2 a = mask_quad_to_h4(src[0]);
        uint2 b = mask_quad_to_h4(src[1]);
        reinterpret_cast<uint4*>(g_wh)[u] = make_uint4(a.x, a.y, b.x, b.y);
    }
    __syncthreads();
    __threadfence();
    if (tid == 0) atomicAdd(&g_done_w, 1);

    // ---- phases 1..128: x row-blocks (128 rows = 262144 floats = 32768 u) --
    for (int blk = 0; blk < 128; blk++) {
        const size_t base = (size_t)blk * (128 * KDIM);   // floats
        const size_t u = base / 8 + gt;                   // exactly 1 unit/thread
        const float4* src = reinterpret_cast<const float4*>(x) + u * 2;
        float4 v0 = src[0], v1 = src[1];
        reinterpret_cast<uint4*>(g_xh)[u] =
            make_uint4(f2h2(v0.x, v0.y), f2h2(v0.z, v0.w),
                       f2h2(v1.x, v1.y), f2h2(v1.z, v1.w));
        __syncthreads();
        __threadfence();
        if (tid == 0) atomicAdd(&g_done_x[blk], 1);
    }
}

// ===========================================================================
// Consumer GEMM (R8-proven)
// ===========================================================================
__device__ __forceinline__ void load_stage(uint32_t sb, int slot, int chunk,
                                           int bm, int bn, int tid) {
    const int k0 = chunk * BKE;
    const uint32_t st = sb + slot * STAGE_SZ;
    #pragma unroll
    for (int t = tid; t < 1024; t += NTH) {       // A: 128 rows x 8 cells
        int row = t >> 3, c = t & 7;
        uint32_t so = (uint32_t)(row << 7) + ((c ^ (row & 7)) << 4);
        cp16(st + STG_A + so, g_xh + (size_t)(bm * BM + row) * KDIM + k0 + c * 8);
    }
    #pragma unroll
    for (int t = tid; t < 1024; t += NTH) {       // B
        int row = t >> 3, c = t & 7;
        uint32_t so = (uint32_t)(row << 7) + ((c ^ (row & 7)) << 4);
        cp16(st + STG_B + so, g_wh + (size_t)(bn * BN + row) * KDIM + k0 + c * 8);
    }
}

__global__ __launch_bounds__(NTH, 2)
void fused_kernel(const float* __restrict__ x,
                  const float* __restrict__ w,
                  const float* __restrict__ bias,
                  float* __restrict__ C) {
    extern __shared__ char smem[];
    const int tid = threadIdx.x;

    if (blockIdx.x < NPREP) {
        producer_body(x, w, blockIdx.x, tid);
        return;
    }

    const uint32_t sb = smem_u32(smem);
    const int wid = tid >> 5;
    const int lid = tid & 31;
    const int t = blockIdx.x - NPREP;
    const int bn = t & 15;
    const int bm = t >> 4;

    // one-time gate: need all of w + x row-block bm
    if (tid == 0) {
        while (((volatile int*)&g_done_w)[0] < NPREP) {}
        while (((volatile int*)g_done_x)[bm] < NPREP) {}
    }
    __syncthreads();

    const int wm = wid >> 2;
    const int wn = wid & 3;

    const int a_r  = lid & 15;
    const int a_ch = lid >> 4;
    const int b_r  = (lid & 7) + ((lid >> 4) << 3);
    const int b_ch = (lid >> 3) & 1;

    float acc[4][4][4];
    #pragma unroll
    for (int i = 0; i < 4; i++)
        #pragma unroll
        for (int j = 0; j < 4; j++)
            #pragma unroll
            for (int r = 0; r < 4; r++)
                acc[i][j][r] = 0.0f;

    const int NIT = KDIM / BKE;       // 32
    load_stage(sb, 0, 0, bm, bn, tid); CP_COMMIT();
    load_stage(sb, 1, 1, bm, bn, tid); CP_COMMIT();

    int s = 0, sl = 2;
    for (int i = 0; i < NIT; i++) {
        CP_WAIT1();
        __syncthreads();
        if (i + 2 < NIT) load_stage(sb, sl, i + 2, bm, bn, tid);
        CP_COMMIT();

        const uint32_t A = sb + s * STAGE_SZ + STG_A;
        const uint32_t B = sb + s * STAGE_SZ + STG_B;
        #pragma unroll
        for (int kk = 0; kk < 4; kk++) {
            uint32_t af[4][4], bf[4][2];
            #pragma unroll
            for (int mt = 0; mt < 4; mt++) {
                int row = wm * 64 + mt * 16 + a_r;
                int c = (kk << 1) + a_ch;
                ldm4(af[mt], A + (row << 7) + ((c ^ (row & 7)) << 4));
            }
            #pragma unroll
            for (int bt = 0; bt < 2; bt++) {
                int row = wn * 32 + bt * 16 + b_r;
                int c = (kk << 1) + b_ch;
                uint32_t rb[4];
                ldm4(rb, B + (row << 7) + ((c ^ (row & 7)) << 4));
                bf[2 * bt + 0][0] = rb[0]; bf[2 * bt + 0][1] = rb[1];
                bf[2 * bt + 1][0] = rb[2]; bf[2 * bt + 1][1] = rb[3];
            }
            #pragma unroll
            for (int mt = 0; mt < 4; mt++)
                #pragma unroll
                for (int nt = 0; nt < 4; nt++)
                    mma16816(acc[mt][nt], af[mt], bf[nt][0], bf[nt][1]);
        }
        s  = (s  == NSTAGE - 1) ? 0 : s + 1;
        sl = (sl == NSTAGE - 1) ? 0 : sl + 1;
    }

    // ---------------- epilogue ----------------------------------------------
    CP_WAIT0();
    __syncthreads();
    float* stg = reinterpret_cast<float*>(smem);   // [128][132]
    #pragma unroll
    for (int mt = 0; mt < 4; mt++)
        #pragma unroll
        for (int nt = 0; nt < 4; nt++) {
            int r0 = wm * 64 + mt * 16 + (lid >> 2);
            int col = wn * 32 + nt * 8 + ((lid & 3) << 1);
            *reinterpret_cast<float2*>(&stg[r0 * 132 + col]) =
                make_float2(acc[mt][nt][0], acc[mt][nt][1]);
            *reinterpret_cast<float2*>(&stg[(r0 + 8) * 132 + col]) =
                make_float2(acc[mt][nt][2], acc[mt][nt][3]);
        }
    __syncthreads();
    {
        int c4 = (tid & 31) << 2;
        int r0 = (tid >> 5) << 4;
        float4 b4 = *reinterpret_cast<const float4*>(bias + bn * BN + c4);
        #pragma unroll
        for (int rr = 0; rr < 16; rr++) {
            int row = r0 + rr;
            float4 v = *reinterpret_cast<float4*>(&stg[row * 132 + c4]);
            v.x += b4.x; v.y += b4.y; v.z += b4.z; v.w += b4.w;
            *reinterpret_cast<float4*>(
                C + (size_t)(bm * BM + row) * NDIM + bn * BN + c4) = v;
        }
    }
}

// ===========================================================================
// Launch
// ===========================================================================
extern "C" void kernel_launch(void* const* d_in, const int* in_sizes, int n_in,
                              void* d_out, int out_size) {
    const float* x    = (const float*)d_in[0];  // [M,K]
    const float* w    = (const float*)d_in[1];  // [N,K]
    const float* bias = (const float*)d_in[2];  // [N]
    float* out = (float*)d_out;                 // [M,N]

    zero_flags_kernel<<<1, 128>>>();

    cudaFuncSetAttribute(fused_kernel,
                         cudaFuncAttributeMaxDynamicSharedMemorySize, SMEM_TOTAL);
    fused_kernel<<<NPREP + NTILES, NTH, SMEM_TOTAL>>>(x, w, bias, out);
}